// round 4
// baseline (speedup 1.0000x reference)
#include <cuda_runtime.h>
#include <cuda_bf16.h>
#include <cstdint>

// out[m,u] = ||x_m||^2 - 2*(x_m . w_u) + ||w_u||^2
// M = 524288, D = 64, U = 64. bf16 mma.sync m16n8k16 for the cross term.
// Fully coalesced: LDG.128 x loads -> swizzled bf16 smem -> ldmatrix.x4;
// B pre-packed uint4 fragments; staged swizzled epilogue -> STG.128.

#define DEPTH 64
#define UNITS 64

__device__ __forceinline__ uint32_t pack_bf16x2(float lo, float hi) {
    uint32_t r;
    asm("cvt.rn.bf16x2.f32 %0, %1, %2;" : "=r"(r) : "f"(hi), "f"(lo));
    return r;
}

__device__ __forceinline__ void mma_bf16(float c[4],
                                         uint32_t a0, uint32_t a1, uint32_t a2, uint32_t a3,
                                         uint32_t b0, uint32_t b1) {
    asm volatile(
        "mma.sync.aligned.m16n8k16.row.col.f32.bf16.bf16.f32 "
        "{%0,%1,%2,%3}, {%4,%5,%6,%7}, {%8,%9}, {%0,%1,%2,%3};"
        : "+f"(c[0]), "+f"(c[1]), "+f"(c[2]), "+f"(c[3])
        : "r"(a0), "r"(a1), "r"(a2), "r"(a3), "r"(b0), "r"(b1));
}

__device__ __forceinline__ void ldsm_x4(uint32_t r[4], uint32_t smem_addr) {
    asm volatile("ldmatrix.sync.aligned.m8n8.x4.shared.b16 {%0,%1,%2,%3}, [%4];"
                 : "=r"(r[0]), "=r"(r[1]), "=r"(r[2]), "=r"(r[3])
                 : "r"(smem_addr));
}

__device__ __forceinline__ uint32_t smem_u32(const void* p) {
    return (uint32_t)__cvta_generic_to_shared(p);
}

__global__ __launch_bounds__(256, 3) void sqdist_kernel(
    const float* __restrict__ x, const float* __restrict__ w,
    float* __restrict__ out)
{
    // B fragments: [nt*2 + kh][lane] -> uint4 = frags for kb=2kh (x,y), kb=2kh+1 (z,w). 8 KB.
    __shared__ uint4 fragB4[16][32];
    __shared__ float w2_s[UNITS];
    // Per-warp scratch: first 2KB = bf16 x tile (swizzled) for ldmatrix,
    // then reused as 2KB float2 epilogue stage. 32 KB total.
    __shared__ __align__(16) char buf[8][4096];

    const int tid  = threadIdx.x;
    const int warp = tid >> 5;
    const int lane = tid & 31;

    // ---- w2 (fp32)
    {
        const int n  = tid >> 2;
        const int dq = (tid & 3) * 16;
        const float* wp = w + n * DEPTH + dq;
        float psum = 0.f;
        #pragma unroll
        for (int i = 0; i < 4; i++) {
            float4 v = reinterpret_cast<const float4*>(wp)[i];
            psum += v.x * v.x + v.y * v.y + v.z * v.z + v.w * v.w;
        }
        psum += __shfl_xor_sync(0xffffffffu, psum, 1);
        psum += __shfl_xor_sync(0xffffffffu, psum, 2);
        if ((tid & 3) == 0) w2_s[n] = psum;
    }

    // ---- Pack w into uint4 B-fragments (512 entries, 2 per thread).
    #pragma unroll
    for (int e = tid; e < 512; e += 256) {
        const int l   = e & 31;
        const int idx = e >> 5;          // 0..15 = nt*2 + kh
        const int kh  = idx & 1;
        const int nt  = idx >> 1;
        const int n   = nt * 8 + (l >> 2);
        const int k0  = (2 * kh) * 16 + (l & 3) * 2;   // kb = 2kh
        const float* wn = w + n * DEPTH;
        float2 a0 = *reinterpret_cast<const float2*>(wn + k0);
        float2 a1 = *reinterpret_cast<const float2*>(wn + k0 + 8);
        float2 b0 = *reinterpret_cast<const float2*>(wn + k0 + 16);
        float2 b1 = *reinterpret_cast<const float2*>(wn + k0 + 24);
        uint4 f;
        f.x = pack_bf16x2(a0.x, a0.y);
        f.y = pack_bf16x2(a1.x, a1.y);
        f.z = pack_bf16x2(b0.x, b0.y);
        f.w = pack_bf16x2(b1.x, b1.y);
        fragB4[idx][l] = f;
    }
    __syncthreads();

    const int g  = lane >> 2;   // 0..7
    const int t4 = lane & 3;    // 0..3
    const long row0 = (long)blockIdx.x * 128 + warp * 16;

    // ---- Coalesced x load: lane -> (row = lane/2, half = lane&1), 8 x LDG.128.
    float s;  // full row sum of x^2 (valid on both lanes of a pair)
    {
        const int row_l = lane >> 1;
        const int half  = lane & 1;
        const float4* xp4 = reinterpret_cast<const float4*>(
            x + (row0 + row_l) * DEPTH + half * 32);
        float4 v[8];
        #pragma unroll
        for (int i = 0; i < 8; i++) v[i] = xp4[i];

        s = 0.f;
        #pragma unroll
        for (int i = 0; i < 8; i++)
            s += v[i].x * v[i].x + v[i].y * v[i].y + v[i].z * v[i].z + v[i].w * v[i].w;
        s += __shfl_xor_sync(0xffffffffu, s, 1);

        // Convert to bf16 and store swizzled (conflict-free: extra (row&8) XOR).
        char* base = buf[warp] + row_l * 128;
        const int rx = (row_l & 7) ^ ((row_l & 8) >> 1);
        #pragma unroll
        for (int c = 0; c < 4; c++) {
            uint4 chunk;
            chunk.x = pack_bf16x2(v[2*c].x,   v[2*c].y);
            chunk.y = pack_bf16x2(v[2*c].z,   v[2*c].w);
            chunk.z = pack_bf16x2(v[2*c+1].x, v[2*c+1].y);
            chunk.w = pack_bf16x2(v[2*c+1].z, v[2*c+1].w);
            const int phys = (half * 4 + c) ^ rx;
            *reinterpret_cast<uint4*>(base + phys * 16) = chunk;
        }
    }
    __syncwarp();

    // ---- A fragments via ldmatrix.x4 (one per kb).
    uint32_t ab[4][4];
    {
        const int row   = (lane & 7) + ((lane >> 3) & 1) * 8;
        const int chsel = (lane >> 4);
        const int rx    = (row & 7) ^ ((row & 8) >> 1);
        const uint32_t base = smem_u32(buf[warp] + row * 128);
        #pragma unroll
        for (int kb = 0; kb < 4; kb++) {
            const int phys = (2 * kb + chsel) ^ rx;
            ldsm_x4(ab[kb], base + phys * 16);
        }
    }

    // ---- x2 values for this lane's output rows.
    const float p_lo = __shfl_sync(0xffffffffu, s, 2 * g);
    const float p_hi = __shfl_sync(0xffffffffu, s, 2 * g + 16);

    // ---- GEMM: 8 n-tiles x 4 k-blocks (B frags as uint4).
    float acc[8][4];
    #pragma unroll
    for (int nt = 0; nt < 8; nt++) {
        acc[nt][0] = acc[nt][1] = acc[nt][2] = acc[nt][3] = 0.f;
        uint4 bA = fragB4[nt * 2][lane];
        mma_bf16(acc[nt], ab[0][0], ab[0][1], ab[0][2], ab[0][3], bA.x, bA.y);
        mma_bf16(acc[nt], ab[1][0], ab[1][1], ab[1][2], ab[1][3], bA.z, bA.w);
        uint4 bB = fragB4[nt * 2 + 1][lane];
        mma_bf16(acc[nt], ab[2][0], ab[2][1], ab[2][2], ab[2][3], bB.x, bB.y);
        mma_bf16(acc[nt], ab[3][0], ab[3][1], ab[3][2], ab[3][3], bB.z, bB.w);
    }
    __syncwarp();   // x-stage reads done; buf now reused as epilogue stage

    // ---- Epilogue: out = x2 + w2 - 2*acc, staged (R3 scheme).
    float2* stage2 = reinterpret_cast<float2*>(buf[warp]);
    const int jj   = lane & 15;
    const int rhal = lane >> 4;
    #pragma unroll
    for (int pass = 0; pass < 2; pass++) {
        const float p = pass ? p_hi : p_lo;
        #pragma unroll
        for (int nt = 0; nt < 8; nt++) {
            const int ucol = nt * 8 + t4 * 2;
            float2 w2v = *reinterpret_cast<const float2*>(&w2_s[ucol]);
            float2 o;
            o.x = p + w2v.x - 2.f * acc[nt][2 * pass];
            o.y = p + w2v.y - 2.f * acc[nt][2 * pass + 1];
            const int sidx = nt * 4 + t4;
            stage2[g * 32 + (sidx ^ ((g & 3) * 4))] = o;
        }
        __syncwarp();
        #pragma unroll
        for (int s8 = 0; s8 < 4; s8++) {
            const int r = s8 * 2 + rhal;
            const int phys = (2 * jj) ^ ((r & 3) * 4);
            float4 v = *reinterpret_cast<const float4*>(&stage2[r * 32 + phys]);
            const long grow = row0 + pass * 8 + r;
            *reinterpret_cast<float4*>(out + grow * UNITS + jj * 4) = v;
        }
        __syncwarp();
    }
}

extern "C" void kernel_launch(void* const* d_in, const int* in_sizes, int n_in,
                              void* d_out, int out_size) {
    const float* x = (const float*)d_in[0];
    const float* w = (const float*)d_in[1];
    float* out = (float*)d_out;
    const int M = in_sizes[0] / DEPTH;   // 524288
    const int grid = M / 128;            // 4096
    sqdist_kernel<<<grid, 256>>>(x, w, out);
}

// round 5
// speedup vs baseline: 2.0877x; 2.0877x over previous
#include <cuda_runtime.h>
#include <cuda_bf16.h>
#include <cstdint>

// out[m,u] = ||x_m||^2 - 2*(x_m . w_u) + ||w_u||^2
// M = 524288, D = 64, U = 64. bf16 mma.sync m16n8k16 for the cross term.
// x loaded tile-contiguously (LDG.128 = 512B/instr), x2 via 16-lane shfl,
// bf16 -> swizzled smem (uint2 stores) -> ldmatrix.x4. B pre-packed uint4.
// Epilogue staged in smem -> contiguous STG.128.

#define DEPTH 64
#define UNITS 64

__device__ __forceinline__ uint32_t pack_bf16x2(float lo, float hi) {
    uint32_t r;
    asm("cvt.rn.bf16x2.f32 %0, %1, %2;" : "=r"(r) : "f"(hi), "f"(lo));
    return r;
}

__device__ __forceinline__ void mma_bf16(float c[4],
                                         uint32_t a0, uint32_t a1, uint32_t a2, uint32_t a3,
                                         uint32_t b0, uint32_t b1) {
    asm volatile(
        "mma.sync.aligned.m16n8k16.row.col.f32.bf16.bf16.f32 "
        "{%0,%1,%2,%3}, {%4,%5,%6,%7}, {%8,%9}, {%0,%1,%2,%3};"
        : "+f"(c[0]), "+f"(c[1]), "+f"(c[2]), "+f"(c[3])
        : "r"(a0), "r"(a1), "r"(a2), "r"(a3), "r"(b0), "r"(b1));
}

__device__ __forceinline__ void ldsm_x4(uint32_t r[4], uint32_t smem_addr) {
    asm volatile("ldmatrix.sync.aligned.m8n8.x4.shared.b16 {%0,%1,%2,%3}, [%4];"
                 : "=r"(r[0]), "=r"(r[1]), "=r"(r[2]), "=r"(r[3])
                 : "r"(smem_addr));
}

__device__ __forceinline__ uint32_t smem_u32(const void* p) {
    return (uint32_t)__cvta_generic_to_shared(p);
}

__global__ __launch_bounds__(256, 3) void sqdist_kernel(
    const float* __restrict__ x, const float* __restrict__ w,
    float* __restrict__ out)
{
    // B fragments: [nt*2 + kh][lane] -> uint4 (kb=2kh in .xy, kb=2kh+1 in .zw). 8 KB.
    __shared__ uint4 fragB4[16][32];
    __shared__ float w2_s[UNITS];
    __shared__ float x2_s[8][16];
    // Per-warp 2KB: bf16 x tile (swizzled) for ldmatrix, reused as epilogue stage.
    __shared__ __align__(16) char buf[8][2048];

    const int tid  = threadIdx.x;
    const int warp = tid >> 5;
    const int lane = tid & 31;

    // ---- w2 (fp32)
    {
        const int n  = tid >> 2;
        const int dq = (tid & 3) * 16;
        const float* wp = w + n * DEPTH + dq;
        float psum = 0.f;
        #pragma unroll
        for (int i = 0; i < 4; i++) {
            float4 v = reinterpret_cast<const float4*>(wp)[i];
            psum += v.x * v.x + v.y * v.y + v.z * v.z + v.w * v.w;
        }
        psum += __shfl_xor_sync(0xffffffffu, psum, 1);
        psum += __shfl_xor_sync(0xffffffffu, psum, 2);
        if ((tid & 3) == 0) w2_s[n] = psum;
    }

    // ---- Pack w into uint4 B-fragments (512 entries, 2 per thread).
    #pragma unroll
    for (int e = tid; e < 512; e += 256) {
        const int l   = e & 31;
        const int idx = e >> 5;          // nt*2 + kh
        const int kh  = idx & 1;
        const int nt  = idx >> 1;
        const int n   = nt * 8 + (l >> 2);
        const int k0  = (2 * kh) * 16 + (l & 3) * 2;
        const float* wn = w + n * DEPTH;
        float2 a0 = *reinterpret_cast<const float2*>(wn + k0);
        float2 a1 = *reinterpret_cast<const float2*>(wn + k0 + 8);
        float2 b0 = *reinterpret_cast<const float2*>(wn + k0 + 16);
        float2 b1 = *reinterpret_cast<const float2*>(wn + k0 + 24);
        uint4 f;
        f.x = pack_bf16x2(a0.x, a0.y);
        f.y = pack_bf16x2(a1.x, a1.y);
        f.z = pack_bf16x2(b0.x, b0.y);
        f.w = pack_bf16x2(b1.x, b1.y);
        fragB4[idx][l] = f;
    }
    __syncthreads();

    const int g  = lane >> 2;   // 0..7
    const int t4 = lane & 3;    // 0..3
    const long row0 = (long)blockIdx.x * 128 + warp * 16;

    // ---- Tile-contiguous x load: lane l, iter i -> float4 #(i*32+l) of the
    //      4KB warp tile. Each LDG.128 instruction covers contiguous 512B.
    float s[8];
    {
        const float4* xt = reinterpret_cast<const float4*>(x + row0 * DEPTH);
        #pragma unroll
        for (int i = 0; i < 8; i++) {
            const int ci = i * 32 + lane;          // float4 index in tile
            float4 v = xt[ci];
            s[i] = v.x * v.x + v.y * v.y + v.z * v.z + v.w * v.w;
            // bf16 pack (8 bytes) -> swizzled tile position
            const int r     = ci >> 4;             // row 0..15 (lanes<16: 2i, else 2i+1)
            const int col4  = ci & 15;             // float4 within row
            const int ch    = col4 >> 1;           // 16B chunk 0..7
            const int half8 = col4 & 1;            // which 8B of the chunk
            const int rx    = (r & 7) ^ ((r & 8) >> 1);
            uint2 h;
            h.x = pack_bf16x2(v.x, v.y);
            h.y = pack_bf16x2(v.z, v.w);
            *reinterpret_cast<uint2*>(buf[warp] + r * 128 + ((ch ^ rx) * 16) + half8 * 8) = h;
        }
        // 16-lane reductions: lanes 0-15 own row 2i, lanes 16-31 own row 2i+1.
        #pragma unroll
        for (int i = 0; i < 8; i++) {
            s[i] += __shfl_xor_sync(0xffffffffu, s[i], 1);
            s[i] += __shfl_xor_sync(0xffffffffu, s[i], 2);
            s[i] += __shfl_xor_sync(0xffffffffu, s[i], 4);
            s[i] += __shfl_xor_sync(0xffffffffu, s[i], 8);
        }
        if (lane == 0) {
            #pragma unroll
            for (int i = 0; i < 8; i++) x2_s[warp][2 * i] = s[i];
        } else if (lane == 16) {
            #pragma unroll
            for (int i = 0; i < 8; i++) x2_s[warp][2 * i + 1] = s[i];
        }
    }
    __syncwarp();

    // ---- A fragments via ldmatrix.x4 (one per kb).
    uint32_t ab[4][4];
    {
        const int row   = (lane & 7) + ((lane >> 3) & 1) * 8;
        const int chsel = (lane >> 4);
        const int rx    = (row & 7) ^ ((row & 8) >> 1);
        const uint32_t base = smem_u32(buf[warp] + row * 128);
        #pragma unroll
        for (int kb = 0; kb < 4; kb++) {
            const int phys = (2 * kb + chsel) ^ rx;
            ldsm_x4(ab[kb], base + phys * 16);
        }
    }

    const float p_lo = x2_s[warp][g];
    const float p_hi = x2_s[warp][g + 8];

    // ---- GEMM: 8 n-tiles x 4 k-blocks.
    float acc[8][4];
    #pragma unroll
    for (int nt = 0; nt < 8; nt++) {
        acc[nt][0] = acc[nt][1] = acc[nt][2] = acc[nt][3] = 0.f;
        uint4 bA = fragB4[nt * 2][lane];
        mma_bf16(acc[nt], ab[0][0], ab[0][1], ab[0][2], ab[0][3], bA.x, bA.y);
        mma_bf16(acc[nt], ab[1][0], ab[1][1], ab[1][2], ab[1][3], bA.z, bA.w);
        uint4 bB = fragB4[nt * 2 + 1][lane];
        mma_bf16(acc[nt], ab[2][0], ab[2][1], ab[2][2], ab[2][3], bB.x, bB.y);
        mma_bf16(acc[nt], ab[3][0], ab[3][1], ab[3][2], ab[3][3], bB.z, bB.w);
    }
    __syncwarp();   // bf16 tile reads done; buf reused as epilogue stage

    // ---- Epilogue: out = x2 + w2 - 2*acc, staged swizzled -> STG.128.
    float2* stage2 = reinterpret_cast<float2*>(buf[warp]);
    const int jj   = lane & 15;
    const int rhal = lane >> 4;
    #pragma unroll
    for (int pass = 0; pass < 2; pass++) {
        const float p = pass ? p_hi : p_lo;
        #pragma unroll
        for (int nt = 0; nt < 8; nt++) {
            const int ucol = nt * 8 + t4 * 2;
            float2 w2v = *reinterpret_cast<const float2*>(&w2_s[ucol]);
            float2 o;
            o.x = p + w2v.x - 2.f * acc[nt][2 * pass];
            o.y = p + w2v.y - 2.f * acc[nt][2 * pass + 1];
            const int sidx = nt * 4 + t4;
            stage2[g * 32 + (sidx ^ ((g & 3) * 4))] = o;
        }
        __syncwarp();
        #pragma unroll
        for (int s8 = 0; s8 < 4; s8++) {
            const int r = s8 * 2 + rhal;
            const int phys = (2 * jj) ^ ((r & 3) * 4);
            float4 v = *reinterpret_cast<const float4*>(&stage2[r * 32 + phys]);
            const long grow = row0 + pass * 8 + r;
            *reinterpret_cast<float4*>(out + grow * UNITS + jj * 4) = v;
        }
        __syncwarp();
    }
}

extern "C" void kernel_launch(void* const* d_in, const int* in_sizes, int n_in,
                              void* d_out, int out_size) {
    const float* x = (const float*)d_in[0];
    const float* w = (const float*)d_in[1];
    float* out = (float*)d_out;
    const int M = in_sizes[0] / DEPTH;   // 524288
    const int grid = M / 128;            // 4096
    sqdist_kernel<<<grid, 256>>>(x, w, out);
}

// round 6
// speedup vs baseline: 2.1592x; 1.0343x over previous
#include <cuda_runtime.h>
#include <cuda_bf16.h>
#include <cstdint>

// out[m,u] = ||x_m||^2 - 2*(x_m . w_u) + ||w_u||^2
// M = 524288, D = 64, U = 64. bf16 mma.sync m16n8k16 for the cross term.
// Each warp now owns TWO 16-row m-tiles (32 rows) so every B-fragment smem
// read is amortized across both tiles. x loaded tile-contiguously (streaming),
// bf16 -> swizzled smem -> ldmatrix.x4; staged swizzled epilogue -> STG.128.

#define DEPTH 64
#define UNITS 64

__device__ __forceinline__ uint32_t pack_bf16x2(float lo, float hi) {
    uint32_t r;
    asm("cvt.rn.bf16x2.f32 %0, %1, %2;" : "=r"(r) : "f"(hi), "f"(lo));
    return r;
}

__device__ __forceinline__ void mma_bf16(float c[4],
                                         uint32_t a0, uint32_t a1, uint32_t a2, uint32_t a3,
                                         uint32_t b0, uint32_t b1) {
    asm volatile(
        "mma.sync.aligned.m16n8k16.row.col.f32.bf16.bf16.f32 "
        "{%0,%1,%2,%3}, {%4,%5,%6,%7}, {%8,%9}, {%0,%1,%2,%3};"
        : "+f"(c[0]), "+f"(c[1]), "+f"(c[2]), "+f"(c[3])
        : "r"(a0), "r"(a1), "r"(a2), "r"(a3), "r"(b0), "r"(b1));
}

__device__ __forceinline__ void ldsm_x4(uint32_t r[4], uint32_t smem_addr) {
    asm volatile("ldmatrix.sync.aligned.m8n8.x4.shared.b16 {%0,%1,%2,%3}, [%4];"
                 : "=r"(r[0]), "=r"(r[1]), "=r"(r[2]), "=r"(r[3])
                 : "r"(smem_addr));
}

__device__ __forceinline__ uint32_t smem_u32(const void* p) {
    return (uint32_t)__cvta_generic_to_shared(p);
}

__global__ __launch_bounds__(256, 2) void sqdist_kernel(
    const float* __restrict__ x, const float* __restrict__ w,
    float* __restrict__ out)
{
    // B fragments: [nt*2 + kh][lane] -> uint4 (kb=2kh in .xy, kb=2kh+1 in .zw). 8 KB.
    __shared__ uint4 fragB4[16][32];
    __shared__ float w2_s[UNITS];
    __shared__ float x2_s[8][32];
    // Per-warp 2KB: bf16 x tile (swizzled) for ldmatrix, reused as epilogue stage.
    __shared__ __align__(16) char buf[8][2048];

    const int tid  = threadIdx.x;
    const int warp = tid >> 5;
    const int lane = tid & 31;

    // ---- w2 (fp32)
    {
        const int n  = tid >> 2;
        const int dq = (tid & 3) * 16;
        const float* wp = w + n * DEPTH + dq;
        float psum = 0.f;
        #pragma unroll
        for (int i = 0; i < 4; i++) {
            float4 v = reinterpret_cast<const float4*>(wp)[i];
            psum += v.x * v.x + v.y * v.y + v.z * v.z + v.w * v.w;
        }
        psum += __shfl_xor_sync(0xffffffffu, psum, 1);
        psum += __shfl_xor_sync(0xffffffffu, psum, 2);
        if ((tid & 3) == 0) w2_s[n] = psum;
    }

    // ---- Pack w into uint4 B-fragments (512 entries, 2 per thread).
    #pragma unroll
    for (int e = tid; e < 512; e += 256) {
        const int l   = e & 31;
        const int idx = e >> 5;          // nt*2 + kh
        const int kh  = idx & 1;
        const int nt  = idx >> 1;
        const int n   = nt * 8 + (l >> 2);
        const int k0  = (2 * kh) * 16 + (l & 3) * 2;
        const float* wn = w + n * DEPTH;
        float2 a0 = *reinterpret_cast<const float2*>(wn + k0);
        float2 a1 = *reinterpret_cast<const float2*>(wn + k0 + 8);
        float2 b0 = *reinterpret_cast<const float2*>(wn + k0 + 16);
        float2 b1 = *reinterpret_cast<const float2*>(wn + k0 + 24);
        uint4 f;
        f.x = pack_bf16x2(a0.x, a0.y);
        f.y = pack_bf16x2(a1.x, a1.y);
        f.z = pack_bf16x2(b0.x, b0.y);
        f.w = pack_bf16x2(b1.x, b1.y);
        fragB4[idx][l] = f;
    }
    __syncthreads();

    const int g  = lane >> 2;   // 0..7
    const int t4 = lane & 3;    // 0..3
    const long row0 = (long)blockIdx.x * 256 + warp * 32;   // 32 rows per warp

    // ---- Per 16-row tile: tile-contiguous streaming load, x2, bf16 -> smem,
    //      ldmatrix.x4 A-fragments. Done twice (tiles 0 and 1).
    uint32_t ab[2][4][4];
    #pragma unroll
    for (int t = 0; t < 2; t++) {
        const float4* xt = reinterpret_cast<const float4*>(x + (row0 + 16 * t) * DEPTH);
        float s[8];
        #pragma unroll
        for (int i = 0; i < 8; i++) {
            const int ci = i * 32 + lane;          // float4 index in 4KB tile
            float4 v = __ldcs(&xt[ci]);
            s[i] = v.x * v.x + v.y * v.y + v.z * v.z + v.w * v.w;
            const int r     = ci >> 4;             // row 0..15
            const int col4  = ci & 15;
            const int ch    = col4 >> 1;
            const int half8 = col4 & 1;
            const int rx    = (r & 7) ^ ((r & 8) >> 1);
            uint2 h;
            h.x = pack_bf16x2(v.x, v.y);
            h.y = pack_bf16x2(v.z, v.w);
            *reinterpret_cast<uint2*>(buf[warp] + r * 128 + ((ch ^ rx) * 16) + half8 * 8) = h;
        }
        #pragma unroll
        for (int i = 0; i < 8; i++) {
            s[i] += __shfl_xor_sync(0xffffffffu, s[i], 1);
            s[i] += __shfl_xor_sync(0xffffffffu, s[i], 2);
            s[i] += __shfl_xor_sync(0xffffffffu, s[i], 4);
            s[i] += __shfl_xor_sync(0xffffffffu, s[i], 8);
        }
        if (lane == 0) {
            #pragma unroll
            for (int i = 0; i < 8; i++) x2_s[warp][16 * t + 2 * i] = s[i];
        } else if (lane == 16) {
            #pragma unroll
            for (int i = 0; i < 8; i++) x2_s[warp][16 * t + 2 * i + 1] = s[i];
        }
        __syncwarp();

        {
            const int row   = (lane & 7) + ((lane >> 3) & 1) * 8;
            const int chsel = (lane >> 4);
            const int rx    = (row & 7) ^ ((row & 8) >> 1);
            const uint32_t base = smem_u32(buf[warp] + row * 128);
            #pragma unroll
            for (int kb = 0; kb < 4; kb++) {
                const int phys = (2 * kb + chsel) ^ rx;
                ldsm_x4(ab[t][kb], base + phys * 16);
            }
        }
        __syncwarp();   // tile reads done before buf is overwritten (t=1 / stage)
    }

    // ---- GEMM: 8 n-tiles x 4 k-blocks x 2 m-tiles. B frags read ONCE per pair.
    float acc[2][8][4];
    #pragma unroll
    for (int nt = 0; nt < 8; nt++) {
        #pragma unroll
        for (int t = 0; t < 2; t++)
            acc[t][nt][0] = acc[t][nt][1] = acc[t][nt][2] = acc[t][nt][3] = 0.f;
        uint4 bA = fragB4[nt * 2][lane];
        uint4 bB = fragB4[nt * 2 + 1][lane];
        #pragma unroll
        for (int t = 0; t < 2; t++) {
            mma_bf16(acc[t][nt], ab[t][0][0], ab[t][0][1], ab[t][0][2], ab[t][0][3], bA.x, bA.y);
            mma_bf16(acc[t][nt], ab[t][1][0], ab[t][1][1], ab[t][1][2], ab[t][1][3], bA.z, bA.w);
            mma_bf16(acc[t][nt], ab[t][2][0], ab[t][2][1], ab[t][2][2], ab[t][2][3], bB.x, bB.y);
            mma_bf16(acc[t][nt], ab[t][3][0], ab[t][3][1], ab[t][3][2], ab[t][3][3], bB.z, bB.w);
        }
    }
    __syncwarp();

    // ---- Epilogue per tile: out = x2 + w2 - 2*acc, staged swizzled -> STG.128.
    float2* stage2 = reinterpret_cast<float2*>(buf[warp]);
    const int jj   = lane & 15;
    const int rhal = lane >> 4;
    #pragma unroll
    for (int t = 0; t < 2; t++) {
        const float p_lo = x2_s[warp][16 * t + g];
        const float p_hi = x2_s[warp][16 * t + g + 8];
        #pragma unroll
        for (int pass = 0; pass < 2; pass++) {
            const float p = pass ? p_hi : p_lo;
            #pragma unroll
            for (int nt = 0; nt < 8; nt++) {
                const int ucol = nt * 8 + t4 * 2;
                float2 w2v = *reinterpret_cast<const float2*>(&w2_s[ucol]);
                float2 o;
                o.x = p + w2v.x - 2.f * acc[t][nt][2 * pass];
                o.y = p + w2v.y - 2.f * acc[t][nt][2 * pass + 1];
                const int sidx = nt * 4 + t4;
                stage2[g * 32 + (sidx ^ ((g & 3) * 4))] = o;
            }
            __syncwarp();
            #pragma unroll
            for (int s8 = 0; s8 < 4; s8++) {
                const int r = s8 * 2 + rhal;
                const int phys = (2 * jj) ^ ((r & 3) * 4);
                float4 v = *reinterpret_cast<const float4*>(&stage2[r * 32 + phys]);
                const long grow = row0 + 16 * t + pass * 8 + r;
                __stcs(reinterpret_cast<float4*>(out + grow * UNITS + jj * 4), v);
            }
            __syncwarp();
        }
    }
}

extern "C" void kernel_launch(void* const* d_in, const int* in_sizes, int n_in,
                              void* d_out, int out_size) {
    const float* x = (const float*)d_in[0];
    const float* w = (const float*)d_in[1];
    float* out = (float*)d_out;
    const int M = in_sizes[0] / DEPTH;   // 524288
    const int grid = M / 256;            // 2048 (each CTA covers 256 rows)
    sqdist_kernel<<<grid, 256>>>(x, w, out);
}

// round 7
// speedup vs baseline: 2.2423x; 1.0385x over previous
#include <cuda_runtime.h>
#include <cuda_bf16.h>
#include <cstdint>

// out[m,u] = ||x_m||^2 - 2*(x_m . w_u) + ||w_u||^2
// M = 524288, D = 64, U = 64. bf16 mma.sync m16n8k16 for the cross term.
// Warp owns TWO 16-row m-tiles with SEPARATE smem buffers -> both tiles'
// loads pipeline without a barrier (MLP ~16). x2 shfl reductions deferred
// past the load/ldsm phase. Epilogue stages 16 rows at once -> 8x STG.128.

#define DEPTH 64
#define UNITS 64

__device__ __forceinline__ uint32_t pack_bf16x2(float lo, float hi) {
    uint32_t r;
    asm("cvt.rn.bf16x2.f32 %0, %1, %2;" : "=r"(r) : "f"(hi), "f"(lo));
    return r;
}

__device__ __forceinline__ void mma_bf16(float c[4],
                                         uint32_t a0, uint32_t a1, uint32_t a2, uint32_t a3,
                                         uint32_t b0, uint32_t b1) {
    asm volatile(
        "mma.sync.aligned.m16n8k16.row.col.f32.bf16.bf16.f32 "
        "{%0,%1,%2,%3}, {%4,%5,%6,%7}, {%8,%9}, {%0,%1,%2,%3};"
        : "+f"(c[0]), "+f"(c[1]), "+f"(c[2]), "+f"(c[3])
        : "r"(a0), "r"(a1), "r"(a2), "r"(a3), "r"(b0), "r"(b1));
}

__device__ __forceinline__ void ldsm_x4(uint32_t r[4], uint32_t smem_addr) {
    asm volatile("ldmatrix.sync.aligned.m8n8.x4.shared.b16 {%0,%1,%2,%3}, [%4];"
                 : "=r"(r[0]), "=r"(r[1]), "=r"(r[2]), "=r"(r[3])
                 : "r"(smem_addr));
}

__device__ __forceinline__ uint32_t smem_u32(const void* p) {
    return (uint32_t)__cvta_generic_to_shared(p);
}

__global__ __launch_bounds__(256, 2) void sqdist_kernel(
    const float* __restrict__ x, const float* __restrict__ w,
    float* __restrict__ out)
{
    // B fragments: [nt*2 + kh][lane] -> uint4 (kb=2kh in .xy, kb=2kh+1 in .zw). 8 KB.
    __shared__ uint4 fragB4[16][32];
    __shared__ float w2_s[UNITS];
    __shared__ float x2_s[8][32];
    // Per-warp 4KB: two 2KB bf16 x-tile buffers (swizzled); reused as 4KB
    // epilogue stage (16 rows x 32 float2). 32 KB total.
    __shared__ __align__(16) char buf[8][4096];

    const int tid  = threadIdx.x;
    const int warp = tid >> 5;
    const int lane = tid & 31;

    // ---- w2 (fp32)
    {
        const int n  = tid >> 2;
        const int dq = (tid & 3) * 16;
        const float* wp = w + n * DEPTH + dq;
        float psum = 0.f;
        #pragma unroll
        for (int i = 0; i < 4; i++) {
            float4 v = reinterpret_cast<const float4*>(wp)[i];
            psum += v.x * v.x + v.y * v.y + v.z * v.z + v.w * v.w;
        }
        psum += __shfl_xor_sync(0xffffffffu, psum, 1);
        psum += __shfl_xor_sync(0xffffffffu, psum, 2);
        if ((tid & 3) == 0) w2_s[n] = psum;
    }

    // ---- Pack w into uint4 B-fragments (512 entries, 2 per thread).
    #pragma unroll
    for (int e = tid; e < 512; e += 256) {
        const int l   = e & 31;
        const int idx = e >> 5;          // nt*2 + kh
        const int kh  = idx & 1;
        const int nt  = idx >> 1;
        const int n   = nt * 8 + (l >> 2);
        const int k0  = (2 * kh) * 16 + (l & 3) * 2;
        const float* wn = w + n * DEPTH;
        float2 a0 = *reinterpret_cast<const float2*>(wn + k0);
        float2 a1 = *reinterpret_cast<const float2*>(wn + k0 + 8);
        float2 b0 = *reinterpret_cast<const float2*>(wn + k0 + 16);
        float2 b1 = *reinterpret_cast<const float2*>(wn + k0 + 24);
        uint4 f;
        f.x = pack_bf16x2(a0.x, a0.y);
        f.y = pack_bf16x2(a1.x, a1.y);
        f.z = pack_bf16x2(b0.x, b0.y);
        f.w = pack_bf16x2(b1.x, b1.y);
        fragB4[idx][l] = f;
    }
    __syncthreads();

    const int g  = lane >> 2;   // 0..7
    const int t4 = lane & 3;    // 0..3
    const long row0 = (long)blockIdx.x * 256 + warp * 32;   // 32 rows per warp

    // ---- Both tiles: tile-contiguous streaming loads + pack/STS, NO barrier
    //      between tiles (separate buffers) -> deep load pipeline.
    float s[2][8];
    #pragma unroll
    for (int t = 0; t < 2; t++) {
        const float4* xt = reinterpret_cast<const float4*>(x + (row0 + 16 * t) * DEPTH);
        char* buft = buf[warp] + t * 2048;
        #pragma unroll
        for (int i = 0; i < 8; i++) {
            const int ci = i * 32 + lane;          // float4 index in 4KB tile
            float4 v = __ldcs(&xt[ci]);
            s[t][i] = v.x * v.x + v.y * v.y + v.z * v.z + v.w * v.w;
            const int r     = ci >> 4;             // row 0..15
            const int col4  = ci & 15;
            const int ch    = col4 >> 1;
            const int half8 = col4 & 1;
            const int rx    = (r & 7) ^ ((r & 8) >> 1);
            uint2 h;
            h.x = pack_bf16x2(v.x, v.y);
            h.y = pack_bf16x2(v.z, v.w);
            *reinterpret_cast<uint2*>(buft + r * 128 + ((ch ^ rx) * 16) + half8 * 8) = h;
        }
    }
    __syncwarp();

    // ---- A fragments via ldmatrix.x4 (both tiles).
    uint32_t ab[2][4][4];
    {
        const int row   = (lane & 7) + ((lane >> 3) & 1) * 8;
        const int chsel = (lane >> 4);
        const int rx    = (row & 7) ^ ((row & 8) >> 1);
        #pragma unroll
        for (int t = 0; t < 2; t++) {
            const uint32_t base = smem_u32(buf[warp] + t * 2048 + row * 128);
            #pragma unroll
            for (int kb = 0; kb < 4; kb++) {
                const int phys = (2 * kb + chsel) ^ rx;
                ldsm_x4(ab[t][kb], base + phys * 16);
            }
        }
    }

    // ---- Deferred x2 reductions (off the load critical path).
    #pragma unroll
    for (int t = 0; t < 2; t++) {
        #pragma unroll
        for (int i = 0; i < 8; i++) {
            s[t][i] += __shfl_xor_sync(0xffffffffu, s[t][i], 1);
            s[t][i] += __shfl_xor_sync(0xffffffffu, s[t][i], 2);
            s[t][i] += __shfl_xor_sync(0xffffffffu, s[t][i], 4);
            s[t][i] += __shfl_xor_sync(0xffffffffu, s[t][i], 8);
        }
    }
    if (lane == 0) {
        #pragma unroll
        for (int t = 0; t < 2; t++)
            #pragma unroll
            for (int i = 0; i < 8; i++) x2_s[warp][16 * t + 2 * i] = s[t][i];
    } else if (lane == 16) {
        #pragma unroll
        for (int t = 0; t < 2; t++)
            #pragma unroll
            for (int i = 0; i < 8; i++) x2_s[warp][16 * t + 2 * i + 1] = s[t][i];
    }

    // ---- GEMM: 8 n-tiles x 4 k-blocks x 2 m-tiles. B frags read ONCE per pair.
    float acc[2][8][4];
    #pragma unroll
    for (int nt = 0; nt < 8; nt++) {
        #pragma unroll
        for (int t = 0; t < 2; t++)
            acc[t][nt][0] = acc[t][nt][1] = acc[t][nt][2] = acc[t][nt][3] = 0.f;
        uint4 bA = fragB4[nt * 2][lane];
        uint4 bB = fragB4[nt * 2 + 1][lane];
        #pragma unroll
        for (int t = 0; t < 2; t++) {
            mma_bf16(acc[t][nt], ab[t][0][0], ab[t][0][1], ab[t][0][2], ab[t][0][3], bA.x, bA.y);
            mma_bf16(acc[t][nt], ab[t][1][0], ab[t][1][1], ab[t][1][2], ab[t][1][3], bA.z, bA.w);
            mma_bf16(acc[t][nt], ab[t][2][0], ab[t][2][1], ab[t][2][2], ab[t][2][3], bB.x, bB.y);
            mma_bf16(acc[t][nt], ab[t][3][0], ab[t][3][1], ab[t][3][2], ab[t][3][3], bB.z, bB.w);
        }
    }
    __syncwarp();   // bf16 tile reads done; buf reused as epilogue stage

    // ---- Epilogue per tile: stage all 16 rows (both passes), then 8x STG.128.
    float2* stage2 = reinterpret_cast<float2*>(buf[warp]);   // 16 rows x 32 float2
    const int jj   = lane & 15;
    const int rhal = lane >> 4;
    #pragma unroll
    for (int t = 0; t < 2; t++) {
        const float p_lo = x2_s[warp][16 * t + g];
        const float p_hi = x2_s[warp][16 * t + g + 8];
        #pragma unroll
        for (int pass = 0; pass < 2; pass++) {
            const float p = pass ? p_hi : p_lo;
            const int rr = pass * 8 + g;
            #pragma unroll
            for (int nt = 0; nt < 8; nt++) {
                const int ucol = nt * 8 + t4 * 2;
                float2 w2v = *reinterpret_cast<const float2*>(&w2_s[ucol]);
                float2 o;
                o.x = p + w2v.x - 2.f * acc[t][nt][2 * pass];
                o.y = p + w2v.y - 2.f * acc[t][nt][2 * pass + 1];
                const int sidx = nt * 4 + t4;
                stage2[rr * 32 + (sidx ^ ((g & 3) * 4))] = o;
            }
        }
        __syncwarp();
        #pragma unroll
        for (int s8 = 0; s8 < 8; s8++) {
            const int r = s8 * 2 + rhal;                 // 0..15
            const int phys = (2 * jj) ^ ((r & 3) * 4);
            float4 v = *reinterpret_cast<const float4*>(&stage2[r * 32 + phys]);
            const long grow = row0 + 16 * t + r;
            __stcs(reinterpret_cast<float4*>(out + grow * UNITS + jj * 4), v);
        }
        __syncwarp();
    }
}

extern "C" void kernel_launch(void* const* d_in, const int* in_sizes, int n_in,
                              void* d_out, int out_size) {
    const float* x = (const float*)d_in[0];
    const float* w = (const float*)d_in[1];
    float* out = (float*)d_out;
    const int M = in_sizes[0] / DEPTH;   // 524288
    const int grid = M / 256;            // 2048 (each CTA covers 256 rows)
    sqdist_kernel<<<grid, 256>>>(x, w, out);
}

// round 8
// speedup vs baseline: 2.3154x; 1.0326x over previous
#include <cuda_runtime.h>
#include <cuda_bf16.h>
#include <cstdint>

// out[m,u] = ||x_m||^2 - 2*(x_m . w_u) + ||w_u||^2
// M = 524288, D = 64, U = 64. bf16 mma.sync m16n8k16 cross term.
// x fetched by cp.async.bulk (32KB contiguous chunks) into double-buffered
// smem stages with mbarrier completion; prefetch depth 2. Warps consume via
// LDS.128, pack bf16 -> swizzled smem -> ldmatrix.x4. B-frags nt0-3 live in
// registers for the whole kernel, nt4-7 in smem. Staged epilogue -> STG.128.

#define DEPTH 64
#define UNITS 64
#define CHUNK_ROWS 128
#define CHUNK_BYTES (CHUNK_ROWS * DEPTH * 4)   // 32768
#define NCHUNK 4                                // rows per CTA = 512

// dynamic smem layout
#define OFF_STAGE  0                    // 2 x 32768
#define OFF_FRAGB  65536                // 16*32*16 = 8192
#define OFF_BUF    73728                // 8 x 2048
#define OFF_W2     90112                // 256
#define OFF_X2     90368                // 512
#define OFF_MBAR   90880                // 16
#define SMEM_TOTAL 90944

__device__ __forceinline__ uint32_t pack_bf16x2(float lo, float hi) {
    uint32_t r;
    asm("cvt.rn.bf16x2.f32 %0, %1, %2;" : "=r"(r) : "f"(hi), "f"(lo));
    return r;
}

__device__ __forceinline__ void mma_bf16(float c[4],
                                         uint32_t a0, uint32_t a1, uint32_t a2, uint32_t a3,
                                         uint32_t b0, uint32_t b1) {
    asm volatile(
        "mma.sync.aligned.m16n8k16.row.col.f32.bf16.bf16.f32 "
        "{%0,%1,%2,%3}, {%4,%5,%6,%7}, {%8,%9}, {%0,%1,%2,%3};"
        : "+f"(c[0]), "+f"(c[1]), "+f"(c[2]), "+f"(c[3])
        : "r"(a0), "r"(a1), "r"(a2), "r"(a3), "r"(b0), "r"(b1));
}

__device__ __forceinline__ void ldsm_x4(uint32_t r[4], uint32_t smem_addr) {
    asm volatile("ldmatrix.sync.aligned.m8n8.x4.shared.b16 {%0,%1,%2,%3}, [%4];"
                 : "=r"(r[0]), "=r"(r[1]), "=r"(r[2]), "=r"(r[3])
                 : "r"(smem_addr));
}

__device__ __forceinline__ uint32_t smem_u32(const void* p) {
    return (uint32_t)__cvta_generic_to_shared(p);
}

__device__ __forceinline__ void mbar_init(uint32_t mbar, uint32_t count) {
    asm volatile("mbarrier.init.shared.b64 [%0], %1;" :: "r"(mbar), "r"(count) : "memory");
}
__device__ __forceinline__ void mbar_expect_tx(uint32_t mbar, uint32_t bytes) {
    asm volatile("mbarrier.arrive.expect_tx.shared.b64 _, [%0], %1;"
                 :: "r"(mbar), "r"(bytes) : "memory");
}
__device__ __forceinline__ void bulk_copy_g2s(uint32_t dst, const void* src,
                                              uint32_t bytes, uint32_t mbar) {
    asm volatile(
        "cp.async.bulk.shared::cluster.global.mbarrier::complete_tx::bytes "
        "[%0], [%1], %2, [%3];"
        :: "r"(dst), "l"(src), "r"(bytes), "r"(mbar) : "memory");
}
__device__ __forceinline__ void mbar_wait(uint32_t mbar, uint32_t parity) {
    uint32_t done;
    asm volatile(
        "{\n\t.reg .pred p;\n\t"
        "mbarrier.try_wait.parity.acquire.cta.shared::cta.b64 p, [%1], %2;\n\t"
        "selp.b32 %0, 1, 0, p;\n\t}"
        : "=r"(done) : "r"(mbar), "r"(parity) : "memory");
    if (!done) {
        asm volatile(
            "{\n\t.reg .pred P1;\n\t"
            "WAIT_LOOP_%=:\n\t"
            "mbarrier.try_wait.parity.acquire.cta.shared::cta.b64 P1, [%0], %1, 0x989680;\n\t"
            "@P1 bra.uni WAIT_DONE_%=;\n\t"
            "bra.uni WAIT_LOOP_%=;\n\t"
            "WAIT_DONE_%=:\n\t}"
            :: "r"(mbar), "r"(parity) : "memory");
    }
}

__global__ __launch_bounds__(256, 2) void sqdist_kernel(
    const float* __restrict__ x, const float* __restrict__ w,
    float* __restrict__ out)
{
    extern __shared__ __align__(16) char smem[];
    float* stage  = reinterpret_cast<float*>(smem + OFF_STAGE);    // 2 x 8192 floats
    uint4 (*fragB4)[32] = reinterpret_cast<uint4(*)[32]>(smem + OFF_FRAGB);
    char*  bufb   = smem + OFF_BUF;                                // 8 x 2048
    float* w2_s   = reinterpret_cast<float*>(smem + OFF_W2);
    float* x2s    = reinterpret_cast<float*>(smem + OFF_X2);       // [8][16]
    const uint32_t mbar0 = smem_u32(smem + OFF_MBAR);
    const uint32_t mbar1 = mbar0 + 8;

    const int tid  = threadIdx.x;
    const int warp = tid >> 5;
    const int lane = tid & 31;

    // ---- w2 (fp32)
    {
        const int n  = tid >> 2;
        const int dq = (tid & 3) * 16;
        const float* wp = w + n * DEPTH + dq;
        float psum = 0.f;
        #pragma unroll
        for (int i = 0; i < 4; i++) {
            float4 v = reinterpret_cast<const float4*>(wp)[i];
            psum += v.x * v.x + v.y * v.y + v.z * v.z + v.w * v.w;
        }
        psum += __shfl_xor_sync(0xffffffffu, psum, 1);
        psum += __shfl_xor_sync(0xffffffffu, psum, 2);
        if ((tid & 3) == 0) w2_s[n] = psum;
    }

    // ---- Pack w into uint4 B-fragments (512 entries, 2 per thread).
    #pragma unroll
    for (int e = tid; e < 512; e += 256) {
        const int l   = e & 31;
        const int idx = e >> 5;          // nt*2 + kh
        const int kh  = idx & 1;
        const int nt  = idx >> 1;
        const int n   = nt * 8 + (l >> 2);
        const int k0  = (2 * kh) * 16 + (l & 3) * 2;
        const float* wn = w + n * DEPTH;
        float2 a0 = *reinterpret_cast<const float2*>(wn + k0);
        float2 a1 = *reinterpret_cast<const float2*>(wn + k0 + 8);
        float2 b0 = *reinterpret_cast<const float2*>(wn + k0 + 16);
        float2 b1 = *reinterpret_cast<const float2*>(wn + k0 + 24);
        uint4 f;
        f.x = pack_bf16x2(a0.x, a0.y);
        f.y = pack_bf16x2(a1.x, a1.y);
        f.z = pack_bf16x2(b0.x, b0.y);
        f.w = pack_bf16x2(b1.x, b1.y);
        fragB4[idx][l] = f;
    }
    if (tid == 0) {
        mbar_init(mbar0, 1);
        mbar_init(mbar1, 1);
    }
    __syncthreads();

    // ---- Kick off prefetch of chunks 0 and 1.
    const long ctarow = (long)blockIdx.x * (CHUNK_ROWS * NCHUNK);
    const float* xbase = x + ctarow * DEPTH;
    if (tid == 0) {
        mbar_expect_tx(mbar0, CHUNK_BYTES);
        bulk_copy_g2s(smem_u32(stage), xbase, CHUNK_BYTES, mbar0);
        mbar_expect_tx(mbar1, CHUNK_BYTES);
        bulk_copy_g2s(smem_u32(stage + 8192), xbase + CHUNK_ROWS * DEPTH,
                      CHUNK_BYTES, mbar1);
    }

    // ---- Hoist B-fragments for nt 0..3 into registers (whole-kernel reuse).
    uint4 Br[8];
    #pragma unroll
    for (int idx = 0; idx < 8; idx++) Br[idx] = fragB4[idx][lane];

    const int g  = lane >> 2;
    const int t4 = lane & 3;
    char* buf = bufb + warp * 2048;
    float2* stage2 = reinterpret_cast<float2*>(buf);
    const int jj   = lane & 15;
    const int rhal = lane >> 4;

    for (int c = 0; c < NCHUNK; c++) {
        const int s = c & 1;
        mbar_wait(s ? mbar1 : mbar0, (c >> 1) & 1);

        // ---- Consume stage: warp's 16-row region, tile-contiguous LDS.128.
        const float4* xt = reinterpret_cast<const float4*>(
            stage + s * 8192 + warp * (16 * DEPTH));
        float sq[8];
        #pragma unroll
        for (int i = 0; i < 8; i++) {
            const int ci = i * 32 + lane;
            float4 v = xt[ci];
            sq[i] = v.x * v.x + v.y * v.y + v.z * v.z + v.w * v.w;
            const int r     = ci >> 4;
            const int col4  = ci & 15;
            const int ch    = col4 >> 1;
            const int half8 = col4 & 1;
            const int rx    = (r & 7) ^ ((r & 8) >> 1);
            uint2 h;
            h.x = pack_bf16x2(v.x, v.y);
            h.y = pack_bf16x2(v.z, v.w);
            *reinterpret_cast<uint2*>(buf + r * 128 + ((ch ^ rx) * 16) + half8 * 8) = h;
        }
        __syncwarp();

        // ---- A fragments via ldmatrix.x4.
        uint32_t ab[4][4];
        {
            const int row   = (lane & 7) + ((lane >> 3) & 1) * 8;
            const int chsel = (lane >> 4);
            const int rx    = (row & 7) ^ ((row & 8) >> 1);
            const uint32_t base = smem_u32(buf + row * 128);
            #pragma unroll
            for (int kb = 0; kb < 4; kb++) {
                const int phys = (2 * kb + chsel) ^ rx;
                ldsm_x4(ab[kb], base + phys * 16);
            }
        }
        __syncthreads();   // all warps done reading stage s

        // ---- Refill stage s with chunk c+2 (overlaps compute below).
        if (tid == 0 && c + 2 < NCHUNK) {
            const uint32_t mb = s ? mbar1 : mbar0;
            mbar_expect_tx(mb, CHUNK_BYTES);
            bulk_copy_g2s(smem_u32(stage + s * 8192),
                          xbase + (long)(c + 2) * CHUNK_ROWS * DEPTH,
                          CHUNK_BYTES, mb);
        }

        // ---- x2 reductions (off load path).
        #pragma unroll
        for (int i = 0; i < 8; i++) {
            sq[i] += __shfl_xor_sync(0xffffffffu, sq[i], 1);
            sq[i] += __shfl_xor_sync(0xffffffffu, sq[i], 2);
            sq[i] += __shfl_xor_sync(0xffffffffu, sq[i], 4);
            sq[i] += __shfl_xor_sync(0xffffffffu, sq[i], 8);
        }
        if (lane == 0) {
            #pragma unroll
            for (int i = 0; i < 8; i++) x2s[warp * 16 + 2 * i] = sq[i];
        } else if (lane == 16) {
            #pragma unroll
            for (int i = 0; i < 8; i++) x2s[warp * 16 + 2 * i + 1] = sq[i];
        }
        __syncwarp();

        // ---- GEMM: nt 0..3 B from registers, nt 4..7 from smem.
        float acc[8][4];
        #pragma unroll
        for (int nt = 0; nt < 4; nt++) {
            acc[nt][0] = acc[nt][1] = acc[nt][2] = acc[nt][3] = 0.f;
            uint4 bA = Br[nt * 2];
            uint4 bB = Br[nt * 2 + 1];
            mma_bf16(acc[nt], ab[0][0], ab[0][1], ab[0][2], ab[0][3], bA.x, bA.y);
            mma_bf16(acc[nt], ab[1][0], ab[1][1], ab[1][2], ab[1][3], bA.z, bA.w);
            mma_bf16(acc[nt], ab[2][0], ab[2][1], ab[2][2], ab[2][3], bB.x, bB.y);
            mma_bf16(acc[nt], ab[3][0], ab[3][1], ab[3][2], ab[3][3], bB.z, bB.w);
        }
        #pragma unroll
        for (int nt = 4; nt < 8; nt++) {
            acc[nt][0] = acc[nt][1] = acc[nt][2] = acc[nt][3] = 0.f;
            uint4 bA = fragB4[nt * 2][lane];
            uint4 bB = fragB4[nt * 2 + 1][lane];
            mma_bf16(acc[nt], ab[0][0], ab[0][1], ab[0][2], ab[0][3], bA.x, bA.y);
            mma_bf16(acc[nt], ab[1][0], ab[1][1], ab[1][2], ab[1][3], bA.z, bA.w);
            mma_bf16(acc[nt], ab[2][0], ab[2][1], ab[2][2], ab[2][3], bB.x, bB.y);
            mma_bf16(acc[nt], ab[3][0], ab[3][1], ab[3][2], ab[3][3], bB.z, bB.w);
        }
        __syncwarp();   // bf16 tile reads done; buf reused as epilogue stage

        // ---- Epilogue: out = x2 + w2 - 2*acc, staged (2 passes of 8 rows).
        const long row0 = ctarow + c * CHUNK_ROWS + warp * 16;
        const float p_lo = x2s[warp * 16 + g];
        const float p_hi = x2s[warp * 16 + g + 8];
        #pragma unroll
        for (int pass = 0; pass < 2; pass++) {
            const float p = pass ? p_hi : p_lo;
            #pragma unroll
            for (int nt = 0; nt < 8; nt++) {
                const int ucol = nt * 8 + t4 * 2;
                float2 w2v = *reinterpret_cast<const float2*>(&w2_s[ucol]);
                float2 o;
                o.x = p + w2v.x - 2.f * acc[nt][2 * pass];
                o.y = p + w2v.y - 2.f * acc[nt][2 * pass + 1];
                const int sidx = nt * 4 + t4;
                stage2[g * 32 + (sidx ^ ((g & 3) * 4))] = o;
            }
            __syncwarp();
            #pragma unroll
            for (int s8 = 0; s8 < 4; s8++) {
                const int r = s8 * 2 + rhal;
                const int phys = (2 * jj) ^ ((r & 3) * 4);
                float4 v = *reinterpret_cast<const float4*>(&stage2[r * 32 + phys]);
                const long grow = row0 + pass * 8 + r;
                __stcs(reinterpret_cast<float4*>(out + grow * UNITS + jj * 4), v);
            }
            __syncwarp();
        }
    }
}

extern "C" void kernel_launch(void* const* d_in, const int* in_sizes, int n_in,
                              void* d_out, int out_size) {
    const float* x = (const float*)d_in[0];
    const float* w = (const float*)d_in[1];
    float* out = (float*)d_out;
    cudaFuncSetAttribute(sqdist_kernel,
                         cudaFuncAttributeMaxDynamicSharedMemorySize, SMEM_TOTAL);
    const int M = in_sizes[0] / DEPTH;                 // 524288
    const int grid = M / (CHUNK_ROWS * NCHUNK);        // 1024
    sqdist_kernel<<<grid, 256, SMEM_TOTAL>>>(x, w, out);
}

// round 9
// speedup vs baseline: 2.3264x; 1.0048x over previous
#include <cuda_runtime.h>
#include <cuda_bf16.h>
#include <cstdint>

// out[m,u] = ||x_m||^2 - 2*(x_m . w_u) + ||w_u||^2
// M = 524288, D = 64, U = 64. bf16 mma.sync m16n8k16 cross term.
// One-shot CTA over 256 rows: both 32KB x-chunks fetched via cp.async.bulk
// issued BEFORE the prologue (overlap), consumed as two 16-row tiles per
// warp with separate bufs (deep pipeline), B-fragment smem reads amortized
// across both tiles, deferred x2 shuffles, staged epilogue -> STG.128.

#define DEPTH 64
#define UNITS 64
#define CHUNK_ROWS 128
#define CHUNK_BYTES (CHUNK_ROWS * DEPTH * 4)   // 32768

// dynamic smem layout
#define OFF_STAGE  0                    // 2 x 32768
#define OFF_BUF    65536                // 8 warps x 4096 (2 x 2KB tile bufs; epilogue stage)
#define OFF_FRAGB  98304                // 16*32*16 = 8192
#define OFF_W2     106496               // 256
#define OFF_X2     106752               // 8*32*4 = 1024
#define OFF_MBAR   107776               // 16
#define SMEM_TOTAL 107800

__device__ __forceinline__ uint32_t pack_bf16x2(float lo, float hi) {
    uint32_t r;
    asm("cvt.rn.bf16x2.f32 %0, %1, %2;" : "=r"(r) : "f"(hi), "f"(lo));
    return r;
}

__device__ __forceinline__ void mma_bf16(float c[4],
                                         uint32_t a0, uint32_t a1, uint32_t a2, uint32_t a3,
                                         uint32_t b0, uint32_t b1) {
    asm volatile(
        "mma.sync.aligned.m16n8k16.row.col.f32.bf16.bf16.f32 "
        "{%0,%1,%2,%3}, {%4,%5,%6,%7}, {%8,%9}, {%0,%1,%2,%3};"
        : "+f"(c[0]), "+f"(c[1]), "+f"(c[2]), "+f"(c[3])
        : "r"(a0), "r"(a1), "r"(a2), "r"(a3), "r"(b0), "r"(b1));
}

__device__ __forceinline__ void ldsm_x4(uint32_t r[4], uint32_t smem_addr) {
    asm volatile("ldmatrix.sync.aligned.m8n8.x4.shared.b16 {%0,%1,%2,%3}, [%4];"
                 : "=r"(r[0]), "=r"(r[1]), "=r"(r[2]), "=r"(r[3])
                 : "r"(smem_addr));
}

__device__ __forceinline__ uint32_t smem_u32(const void* p) {
    return (uint32_t)__cvta_generic_to_shared(p);
}

__device__ __forceinline__ void mbar_init(uint32_t mbar, uint32_t count) {
    asm volatile("mbarrier.init.shared.b64 [%0], %1;" :: "r"(mbar), "r"(count) : "memory");
}
__device__ __forceinline__ void mbar_expect_tx(uint32_t mbar, uint32_t bytes) {
    asm volatile("mbarrier.arrive.expect_tx.shared.b64 _, [%0], %1;"
                 :: "r"(mbar), "r"(bytes) : "memory");
}
__device__ __forceinline__ void bulk_copy_g2s(uint32_t dst, const void* src,
                                              uint32_t bytes, uint32_t mbar) {
    asm volatile(
        "cp.async.bulk.shared::cluster.global.mbarrier::complete_tx::bytes "
        "[%0], [%1], %2, [%3];"
        :: "r"(dst), "l"(src), "r"(bytes), "r"(mbar) : "memory");
}
__device__ __forceinline__ void mbar_wait(uint32_t mbar, uint32_t parity) {
    uint32_t done;
    asm volatile(
        "{\n\t.reg .pred p;\n\t"
        "mbarrier.try_wait.parity.acquire.cta.shared::cta.b64 p, [%1], %2;\n\t"
        "selp.b32 %0, 1, 0, p;\n\t}"
        : "=r"(done) : "r"(mbar), "r"(parity) : "memory");
    if (!done) {
        asm volatile(
            "{\n\t.reg .pred P1;\n\t"
            "WAIT_LOOP_%=:\n\t"
            "mbarrier.try_wait.parity.acquire.cta.shared::cta.b64 P1, [%0], %1, 0x989680;\n\t"
            "@P1 bra.uni WAIT_DONE_%=;\n\t"
            "bra.uni WAIT_LOOP_%=;\n\t"
            "WAIT_DONE_%=:\n\t}"
            :: "r"(mbar), "r"(parity) : "memory");
    }
}

__global__ __launch_bounds__(256, 2) void sqdist_kernel(
    const float* __restrict__ x, const float* __restrict__ w,
    float* __restrict__ out)
{
    extern __shared__ __align__(16) char smem[];
    float* stage = reinterpret_cast<float*>(smem + OFF_STAGE);
    uint4 (*fragB4)[32] = reinterpret_cast<uint4(*)[32]>(smem + OFF_FRAGB);
    float* w2_s  = reinterpret_cast<float*>(smem + OFF_W2);
    float* x2s   = reinterpret_cast<float*>(smem + OFF_X2);   // [8][32]
    const uint32_t mbar0 = smem_u32(smem + OFF_MBAR);
    const uint32_t mbar1 = mbar0 + 8;

    const int tid  = threadIdx.x;
    const int warp = tid >> 5;
    const int lane = tid & 31;

    const long ctarow = (long)blockIdx.x * 256;
    const float* xbase = x + ctarow * DEPTH;

    // ---- Issue both chunk loads FIRST (overlap with prologue).
    if (tid == 0) {
        mbar_init(mbar0, 1);
        mbar_init(mbar1, 1);
        mbar_expect_tx(mbar0, CHUNK_BYTES);
        bulk_copy_g2s(smem_u32(stage), xbase, CHUNK_BYTES, mbar0);
        mbar_expect_tx(mbar1, CHUNK_BYTES);
        bulk_copy_g2s(smem_u32(stage + 8192), xbase + CHUNK_ROWS * DEPTH,
                      CHUNK_BYTES, mbar1);
    }

    // ---- Prologue: w2 (fp32)
    {
        const int n  = tid >> 2;
        const int dq = (tid & 3) * 16;
        const float* wp = w + n * DEPTH + dq;
        float psum = 0.f;
        #pragma unroll
        for (int i = 0; i < 4; i++) {
            float4 v = reinterpret_cast<const float4*>(wp)[i];
            psum += v.x * v.x + v.y * v.y + v.z * v.z + v.w * v.w;
        }
        psum += __shfl_xor_sync(0xffffffffu, psum, 1);
        psum += __shfl_xor_sync(0xffffffffu, psum, 2);
        if ((tid & 3) == 0) w2_s[n] = psum;
    }

    // ---- Prologue: pack w into uint4 B-fragments (512 entries, 2 per thread).
    #pragma unroll
    for (int e = tid; e < 512; e += 256) {
        const int l   = e & 31;
        const int idx = e >> 5;          // nt*2 + kh
        const int kh  = idx & 1;
        const int nt  = idx >> 1;
        const int n   = nt * 8 + (l >> 2);
        const int k0  = (2 * kh) * 16 + (l & 3) * 2;
        const float* wn = w + n * DEPTH;
        float2 a0 = *reinterpret_cast<const float2*>(wn + k0);
        float2 a1 = *reinterpret_cast<const float2*>(wn + k0 + 8);
        float2 b0 = *reinterpret_cast<const float2*>(wn + k0 + 16);
        float2 b1 = *reinterpret_cast<const float2*>(wn + k0 + 24);
        uint4 f;
        f.x = pack_bf16x2(a0.x, a0.y);
        f.y = pack_bf16x2(a1.x, a1.y);
        f.z = pack_bf16x2(b0.x, b0.y);
        f.w = pack_bf16x2(b1.x, b1.y);
        fragB4[idx][l] = f;
    }
    __syncthreads();   // fragB + mbar init visible

    const int g  = lane >> 2;
    const int t4 = lane & 3;
    char* buf = smem + OFF_BUF + warp * 4096;   // 2 x 2KB tile bufs / epilogue stage

    // ---- Consume both tiles (16 rows each) with deep load pipeline.
    float sq[2][8];
    #pragma unroll
    for (int t = 0; t < 2; t++) {
        mbar_wait(t ? mbar1 : mbar0, 0);
        const float4* xt = reinterpret_cast<const float4*>(
            stage + t * 8192 + warp * (16 * DEPTH));
        char* buft = buf + t * 2048;
        #pragma unroll
        for (int i = 0; i < 8; i++) {
            const int ci = i * 32 + lane;
            float4 v = xt[ci];
            sq[t][i] = v.x * v.x + v.y * v.y + v.z * v.z + v.w * v.w;
            const int r     = ci >> 4;
            const int col4  = ci & 15;
            const int ch    = col4 >> 1;
            const int half8 = col4 & 1;
            const int rx    = (r & 7) ^ ((r & 8) >> 1);
            uint2 h;
            h.x = pack_bf16x2(v.x, v.y);
            h.y = pack_bf16x2(v.z, v.w);
            *reinterpret_cast<uint2*>(buft + r * 128 + ((ch ^ rx) * 16) + half8 * 8) = h;
        }
    }
    __syncwarp();

    // ---- A fragments via ldmatrix.x4 (both tiles).
    uint32_t ab[2][4][4];
    {
        const int row   = (lane & 7) + ((lane >> 3) & 1) * 8;
        const int chsel = (lane >> 4);
        const int rx    = (row & 7) ^ ((row & 8) >> 1);
        #pragma unroll
        for (int t = 0; t < 2; t++) {
            const uint32_t base = smem_u32(buf + t * 2048 + row * 128);
            #pragma unroll
            for (int kb = 0; kb < 4; kb++) {
                const int phys = (2 * kb + chsel) ^ rx;
                ldsm_x4(ab[t][kb], base + phys * 16);
            }
        }
    }

    // ---- Deferred x2 reductions.
    #pragma unroll
    for (int t = 0; t < 2; t++) {
        #pragma unroll
        for (int i = 0; i < 8; i++) {
            sq[t][i] += __shfl_xor_sync(0xffffffffu, sq[t][i], 1);
            sq[t][i] += __shfl_xor_sync(0xffffffffu, sq[t][i], 2);
            sq[t][i] += __shfl_xor_sync(0xffffffffu, sq[t][i], 4);
            sq[t][i] += __shfl_xor_sync(0xffffffffu, sq[t][i], 8);
        }
    }
    if (lane == 0) {
        #pragma unroll
        for (int t = 0; t < 2; t++)
            #pragma unroll
            for (int i = 0; i < 8; i++) x2s[warp * 32 + 16 * t + 2 * i] = sq[t][i];
    } else if (lane == 16) {
        #pragma unroll
        for (int t = 0; t < 2; t++)
            #pragma unroll
            for (int i = 0; i < 8; i++) x2s[warp * 32 + 16 * t + 2 * i + 1] = sq[t][i];
    }

    // ---- GEMM: B fragments read ONCE per pair of m-tiles.
    float acc[2][8][4];
    #pragma unroll
    for (int nt = 0; nt < 8; nt++) {
        #pragma unroll
        for (int t = 0; t < 2; t++)
            acc[t][nt][0] = acc[t][nt][1] = acc[t][nt][2] = acc[t][nt][3] = 0.f;
        uint4 bA = fragB4[nt * 2][lane];
        uint4 bB = fragB4[nt * 2 + 1][lane];
        #pragma unroll
        for (int t = 0; t < 2; t++) {
            mma_bf16(acc[t][nt], ab[t][0][0], ab[t][0][1], ab[t][0][2], ab[t][0][3], bA.x, bA.y);
            mma_bf16(acc[t][nt], ab[t][1][0], ab[t][1][1], ab[t][1][2], ab[t][1][3], bA.z, bA.w);
            mma_bf16(acc[t][nt], ab[t][2][0], ab[t][2][1], ab[t][2][2], ab[t][2][3], bB.x, bB.y);
            mma_bf16(acc[t][nt], ab[t][3][0], ab[t][3][1], ab[t][3][2], ab[t][3][3], bB.z, bB.w);
        }
    }
    __syncwarp();   // tile-buf reads done; buf reused as 4KB epilogue stage

    // ---- Epilogue per tile: stage 16 rows, then 8x STG.128.
    float2* stage2 = reinterpret_cast<float2*>(buf);   // 16 rows x 32 float2
    const int jj   = lane & 15;
    const int rhal = lane >> 4;
    #pragma unroll
    for (int t = 0; t < 2; t++) {
        const float p_lo = x2s[warp * 32 + 16 * t + g];
        const float p_hi = x2s[warp * 32 + 16 * t + g + 8];
        #pragma unroll
        for (int pass = 0; pass < 2; pass++) {
            const float p = pass ? p_hi : p_lo;
            const int rr = pass * 8 + g;
            #pragma unroll
            for (int nt = 0; nt < 8; nt++) {
                const int ucol = nt * 8 + t4 * 2;
                float2 w2v = *reinterpret_cast<const float2*>(&w2_s[ucol]);
                float2 o;
                o.x = p + w2v.x - 2.f * acc[t][nt][2 * pass];
                o.y = p + w2v.y - 2.f * acc[t][nt][2 * pass + 1];
                const int sidx = nt * 4 + t4;
                stage2[rr * 32 + (sidx ^ ((g & 3) * 4))] = o;
            }
        }
        __syncwarp();
        const long row0 = ctarow + t * CHUNK_ROWS + warp * 16;
        #pragma unroll
        for (int s8 = 0; s8 < 8; s8++) {
            const int r = s8 * 2 + rhal;
            const int phys = (2 * jj) ^ ((r & 3) * 4);
            float4 v = *reinterpret_cast<const float4*>(&stage2[r * 32 + phys]);
            const long grow = row0 + r;
            __stcs(reinterpret_cast<float4*>(out + grow * UNITS + jj * 4), v);
        }
        __syncwarp();
    }
}

extern "C" void kernel_launch(void* const* d_in, const int* in_sizes, int n_in,
                              void* d_out, int out_size) {
    const float* x = (const float*)d_in[0];
    const float* w = (const float*)d_in[1];
    float* out = (float*)d_out;
    cudaFuncSetAttribute(sqdist_kernel,
                         cudaFuncAttributeMaxDynamicSharedMemorySize, SMEM_TOTAL);
    const int M = in_sizes[0] / DEPTH;   // 524288
    const int grid = M / 256;            // 2048
    sqdist_kernel<<<grid, 256, SMEM_TOTAL>>>(x, w, out);
}